// round 8
// baseline (speedup 1.0000x reference)
#include <cuda_runtime.h>
#include <cuda_fp16.h>

#define NUM_NODES 150000
#define EMB_DIM   64
#define N_EDGES   4000000
#define SCAN_B    1024
#define SCAN_GRID ((NUM_NODES + SCAN_B - 1) / SCAN_B)   // 147
#define NBINS     256

__device__ __forceinline__ unsigned int h2_to_u32(__half2 h) {
    return *reinterpret_cast<unsigned int*>(&h);
}
__device__ __forceinline__ __half2 u32_to_h2(unsigned int u) {
    return *reinterpret_cast<__half2*>(&u);
}

// ---- scratch (static device globals; addresses taken ONLY in device code) ----
__device__ __half g_w16 [NUM_NODES * EMB_DIM];
__device__ __half g_l16A[NUM_NODES * EMB_DIM];
__device__ __half g_l16B[NUM_NODES * EMB_DIM];
__device__ int2   g_csr[N_EDGES];
__device__ int    g_offs[NUM_NODES + 1];
__device__ int    g_cur[NUM_NODES];
__device__ int    g_deg[NUM_NODES];
__device__ float  g_dis[NUM_NODES];
__device__ int    g_part[SCAN_GRID];
__device__ int    g_hist[NBINS];
__device__ int    g_bincur[NBINS];
__device__ int    g_order[NUM_NODES];    // nodes sorted by degree

// ---- fused: zero counters + convert w -> fp16 ----
__global__ void k_init(const float4* __restrict__ w) {
    int i = blockIdx.x * blockDim.x + threadIdx.x;
    if (i < NUM_NODES * EMB_DIM / 4) {
        float4 v = w[i];
        uint2 h;
        h.x = h2_to_u32(__floats2half2_rn(v.x, v.y));
        h.y = h2_to_u32(__floats2half2_rn(v.z, v.w));
        ((uint2*)g_w16)[i] = h;
    }
    if (i < NUM_NODES) { g_deg[i] = 0; g_cur[i] = 0; }
    if (i < NBINS)     { g_hist[i] = 0; g_bincur[i] = 0; }
}

__global__ void k_count_deg(const int* __restrict__ col) {
    int i = blockIdx.x * blockDim.x + threadIdx.x;
    if (i < N_EDGES) atomicAdd(&g_deg[col[i]], 1);
}

// ---- block scan of g_deg into g_offs (local), + deg^-1/2, + degree hist ----
__global__ void k_scan_block() {
    __shared__ int s[SCAN_B];
    int gid = blockIdx.x * SCAN_B + threadIdx.x;
    int v = (gid < NUM_NODES) ? g_deg[gid] : 0;
    s[threadIdx.x] = v;
    __syncthreads();
    for (int off = 1; off < SCAN_B; off <<= 1) {
        int t = (threadIdx.x >= off) ? s[threadIdx.x - off] : 0;
        __syncthreads();
        s[threadIdx.x] += t;
        __syncthreads();
    }
    if (gid < NUM_NODES) {
        g_offs[gid] = s[threadIdx.x] - v;          // block-local exclusive
        g_dis[gid] = (v > 0) ? rsqrtf((float)v) : 0.0f;
        atomicAdd(&g_hist[v < NBINS ? v : NBINS - 1], 1);
    }
    if (threadIdx.x == SCAN_B - 1) g_part[blockIdx.x] = s[SCAN_B - 1];
}

// ---- add cross-block base (reduce partials in-block; no separate scan) ----
__global__ void k_scan_add() {
    __shared__ int red[SCAN_B / 32];
    __shared__ int base_s;
    int tid = threadIdx.x;
    int v = (tid < blockIdx.x) ? g_part[tid] : 0;   // blockIdx.x <= 146 < SCAN_B
    #pragma unroll
    for (int o = 16; o; o >>= 1) v += __shfl_down_sync(0xFFFFFFFFu, v, o);
    if ((tid & 31) == 0) red[tid >> 5] = v;
    __syncthreads();
    if (tid == 0) {
        int t = 0;
        for (int i = 0; i < SCAN_B / 32; ++i) t += red[i];
        base_s = t;
    }
    __syncthreads();
    int gid = blockIdx.x * SCAN_B + tid;
    if (gid < NUM_NODES) g_offs[gid] += base_s;
    if (gid == 0) g_offs[NUM_NODES] = N_EDGES;
}

// ---- counting-sort scatter: nodes ordered by degree ----
__global__ void k_order() {
    __shared__ int hoffs[NBINS];
    // block-local exclusive scan of the (global) histogram — every block
    // redundantly computes it; 256 elems, trivial.
    int t = threadIdx.x;   // blockDim.x == 256
    int hv = g_hist[t];
    hoffs[t] = hv;
    __syncthreads();
    for (int off = 1; off < NBINS; off <<= 1) {
        int tv = (t >= off) ? hoffs[t - off] : 0;
        __syncthreads();
        hoffs[t] += tv;
        __syncthreads();
    }
    int my_excl = hoffs[t] - hv;
    __syncthreads();
    hoffs[t] = my_excl;
    __syncthreads();

    int i = blockIdx.x * blockDim.x + t;
    if (i < NUM_NODES) {
        int d = g_deg[i];
        int b = (d < NBINS) ? d : NBINS - 1;
        int pos = hoffs[b] + atomicAdd(&g_bincur[b], 1);
        g_order[pos] = i;
    }
}

// ---- fill CSR grouped by destination col, norm precomputed ----
__global__ void k_fill(const int* __restrict__ row, const int* __restrict__ col) {
    int e = blockIdx.x * blockDim.x + threadIdx.x;
    if (e >= N_EDGES) return;
    int r = row[e];
    int c = col[e];
    int pos = g_offs[c] + atomicAdd(&g_cur[c], 1);
    g_csr[pos] = make_int2(r, __float_as_int(g_dis[r] * g_dis[c]));
}

// ---- accumulate one fp16 row chunk (8 halves) into 8 fp32 accumulators ----
__device__ __forceinline__ void acc8(float* a, uint4 hv, float nrm) {
    float2 f0 = __half22float2(u32_to_h2(hv.x));
    float2 f1 = __half22float2(u32_to_h2(hv.y));
    float2 f2 = __half22float2(u32_to_h2(hv.z));
    float2 f3 = __half22float2(u32_to_h2(hv.w));
    a[0] += nrm * f0.x; a[1] += nrm * f0.y;
    a[2] += nrm * f1.x; a[3] += nrm * f1.y;
    a[4] += nrm * f2.x; a[5] += nrm * f2.y;
    a[6] += nrm * f3.x; a[7] += nrm * f3.y;
}

// ---- per-layer gather over degree-sorted nodes ----
__global__ void k_gather(int layer,
                         const float4* __restrict__ w,
                         float4* __restrict__ out) {
    int t = blockIdx.x * blockDim.x + threadIdx.x;
    int slot = t >> 3, lane = t & 7;
    if (slot >= NUM_NODES) return;
    int node = g_order[slot];   // same degree as warp-mates -> balanced

    const uint4* src;
    if (layer == 0)      src = (const uint4*)g_w16;
    else if (layer == 1) src = (const uint4*)g_l16A;
    else                 src = (const uint4*)g_l16B;

    int s = g_offs[node], e = g_offs[node + 1];
    float acc[8] = {0.f, 0.f, 0.f, 0.f, 0.f, 0.f, 0.f, 0.f};

    int j = s;
    for (; j + 8 <= e; j += 8) {
        int2 e0 = __ldg(&g_csr[j + 0]);
        int2 e1 = __ldg(&g_csr[j + 1]);
        int2 e2 = __ldg(&g_csr[j + 2]);
        int2 e3 = __ldg(&g_csr[j + 3]);
        int2 e4 = __ldg(&g_csr[j + 4]);
        int2 e5 = __ldg(&g_csr[j + 5]);
        int2 e6 = __ldg(&g_csr[j + 6]);
        int2 e7 = __ldg(&g_csr[j + 7]);
        uint4 v0 = __ldg(&src[e0.x * 8 + lane]);
        uint4 v1 = __ldg(&src[e1.x * 8 + lane]);
        uint4 v2 = __ldg(&src[e2.x * 8 + lane]);
        uint4 v3 = __ldg(&src[e3.x * 8 + lane]);
        uint4 v4 = __ldg(&src[e4.x * 8 + lane]);
        uint4 v5 = __ldg(&src[e5.x * 8 + lane]);
        uint4 v6 = __ldg(&src[e6.x * 8 + lane]);
        uint4 v7 = __ldg(&src[e7.x * 8 + lane]);
        acc8(acc, v0, __int_as_float(e0.y));
        acc8(acc, v1, __int_as_float(e1.y));
        acc8(acc, v2, __int_as_float(e2.y));
        acc8(acc, v3, __int_as_float(e3.y));
        acc8(acc, v4, __int_as_float(e4.y));
        acc8(acc, v5, __int_as_float(e5.y));
        acc8(acc, v6, __int_as_float(e6.y));
        acc8(acc, v7, __int_as_float(e7.y));
    }
    for (; j + 2 <= e; j += 2) {
        int2 ea = __ldg(&g_csr[j]);
        int2 eb = __ldg(&g_csr[j + 1]);
        uint4 va = __ldg(&src[ea.x * 8 + lane]);
        uint4 vb = __ldg(&src[eb.x * 8 + lane]);
        acc8(acc, va, __int_as_float(ea.y));
        acc8(acc, vb, __int_as_float(eb.y));
    }
    if (j < e) {
        int2 pr = __ldg(&g_csr[j]);
        uint4 v = __ldg(&src[pr.x * 8 + lane]);
        acc8(acc, v, __int_as_float(pr.y));
    }

    int i16 = node * 8 + lane;
    if (layer != 2) {
        uint4 h;
        h.x = h2_to_u32(__floats2half2_rn(acc[0], acc[1]));
        h.y = h2_to_u32(__floats2half2_rn(acc[2], acc[3]));
        h.z = h2_to_u32(__floats2half2_rn(acc[4], acc[5]));
        h.w = h2_to_u32(__floats2half2_rn(acc[6], acc[7]));
        if (layer == 0) ((uint4*)g_l16A)[i16] = h;
        else            ((uint4*)g_l16B)[i16] = h;
    }

    int i = node * 16 + lane * 2;
    if (layer == 0) {
        float4 a0 = w[i], a1 = w[i + 1];
        out[i]     = make_float4(a0.x + acc[0], a0.y + acc[1], a0.z + acc[2], a0.w + acc[3]);
        out[i + 1] = make_float4(a1.x + acc[4], a1.y + acc[5], a1.z + acc[6], a1.w + acc[7]);
    } else if (layer == 1) {
        float4 a0 = out[i], a1 = out[i + 1];
        out[i]     = make_float4(a0.x + acc[0], a0.y + acc[1], a0.z + acc[2], a0.w + acc[3]);
        out[i + 1] = make_float4(a1.x + acc[4], a1.y + acc[5], a1.z + acc[6], a1.w + acc[7]);
    } else {
        const float q = 0.25f;
        float4 a0 = out[i], a1 = out[i + 1];
        out[i]     = make_float4(q * (a0.x + acc[0]), q * (a0.y + acc[1]),
                                 q * (a0.z + acc[2]), q * (a0.w + acc[3]));
        out[i + 1] = make_float4(q * (a1.x + acc[4]), q * (a1.y + acc[5]),
                                 q * (a1.z + acc[6]), q * (a1.w + acc[7]));
    }
}

extern "C" void kernel_launch(void* const* d_in, const int* in_sizes, int n_in,
                              void* d_out, int out_size) {
    const int*   edge = (const int*)d_in[0];     // [2, N_EDGES] int32
    const int*   row  = edge;
    const int*   col  = edge + N_EDGES;
    const float* w    = (const float*)d_in[1];   // [NUM_NODES, EMB_DIM] f32
    float*       out  = (float*)d_out;

    const int B = 256;
    const int edges_blk = (N_EDGES + B - 1) / B;
    const int vec_blk   = (NUM_NODES * EMB_DIM / 4 + B - 1) / B;
    const int nodes_blk = (NUM_NODES + B - 1) / B;
    const long long gth = (long long)NUM_NODES * 8;
    const int gather_blk = (int)((gth + B - 1) / B);

    // ---- build CSR + degree-sorted order + fp16 source ----
    k_init<<<vec_blk, B>>>((const float4*)w);
    k_count_deg<<<edges_blk, B>>>(col);
    k_scan_block<<<SCAN_GRID, SCAN_B>>>();
    k_scan_add<<<SCAN_GRID, SCAN_B>>>();
    k_order<<<nodes_blk, B>>>();
    k_fill<<<edges_blk, B>>>(row, col);

    // ---- 3 propagation layers over balanced node order ----
    k_gather<<<gather_blk, B>>>(0, (const float4*)w, (float4*)out);
    k_gather<<<gather_blk, B>>>(1, (const float4*)w, (float4*)out);
    k_gather<<<gather_blk, B>>>(2, (const float4*)w, (float4*)out);
}

// round 9
// speedup vs baseline: 1.5080x; 1.5080x over previous
#include <cuda_runtime.h>
#include <cuda_fp16.h>

#define NUM_NODES 150000
#define EMB_DIM   64
#define N_EDGES   4000000
#define SCAN_B    1024
#define SCAN_GRID ((NUM_NODES + SCAN_B - 1) / SCAN_B)   // 147

__device__ __forceinline__ unsigned int h2_to_u32(__half2 h) {
    return *reinterpret_cast<unsigned int*>(&h);
}
__device__ __forceinline__ __half2 u32_to_h2(unsigned int u) {
    return *reinterpret_cast<__half2*>(&u);
}

// ---- scratch (static device globals; addresses taken ONLY in device code) ----
// y-buffers hold dis-prescaled embeddings: y = dis * embs (fp16)
__device__ __half g_y0[NUM_NODES * EMB_DIM];     // dis * w
__device__ __half g_y1[NUM_NODES * EMB_DIM];     // dis^2 * S1
__device__ __half g_y2[NUM_NODES * EMB_DIM];     // dis^2 * S2
__device__ int    g_csr[N_EDGES];                // row index only (4B!)
__device__ int    g_offs[NUM_NODES + 1];
__device__ int    g_cur[NUM_NODES];
__device__ int    g_deg[NUM_NODES];
__device__ float  g_dis[NUM_NODES];              // deg^-1/2 (0 if deg==0)
__device__ float  g_dinv[NUM_NODES];             // deg^+1/2 (0 if deg==0)
__device__ int    g_part[SCAN_GRID];

__global__ void k_zero() {
    int i = blockIdx.x * blockDim.x + threadIdx.x;
    if (i < NUM_NODES) { g_deg[i] = 0; g_cur[i] = 0; }
}

__global__ void k_count_deg(const int* __restrict__ col) {
    int i = blockIdx.x * blockDim.x + threadIdx.x;
    if (i < N_EDGES) atomicAdd(&g_deg[col[i]], 1);
}

// ---- block-local exclusive scan of g_deg, + dis/dinv ----
__global__ void k_scan_block() {
    __shared__ int s[SCAN_B];
    int gid = blockIdx.x * SCAN_B + threadIdx.x;
    int v = (gid < NUM_NODES) ? g_deg[gid] : 0;
    s[threadIdx.x] = v;
    __syncthreads();
    for (int off = 1; off < SCAN_B; off <<= 1) {
        int t = (threadIdx.x >= off) ? s[threadIdx.x - off] : 0;
        __syncthreads();
        s[threadIdx.x] += t;
        __syncthreads();
    }
    if (gid < NUM_NODES) {
        g_offs[gid] = s[threadIdx.x] - v;
        g_dis[gid]  = (v > 0) ? rsqrtf((float)v) : 0.0f;
        g_dinv[gid] = (v > 0) ? sqrtf((float)v)  : 0.0f;
    }
    if (threadIdx.x == SCAN_B - 1) g_part[blockIdx.x] = s[SCAN_B - 1];
}

// ---- add cross-block base (in-block reduction of preceding partials) ----
__global__ void k_scan_add() {
    __shared__ int red[SCAN_B / 32];
    __shared__ int base_s;
    int tid = threadIdx.x;
    int v = (tid < blockIdx.x) ? g_part[tid] : 0;
    #pragma unroll
    for (int o = 16; o; o >>= 1) v += __shfl_down_sync(0xFFFFFFFFu, v, o);
    if ((tid & 31) == 0) red[tid >> 5] = v;
    __syncthreads();
    if (tid == 0) {
        int t = 0;
        for (int i = 0; i < SCAN_B / 32; ++i) t += red[i];
        base_s = t;
    }
    __syncthreads();
    int gid = blockIdx.x * SCAN_B + tid;
    if (gid < NUM_NODES) g_offs[gid] += base_s;
    if (gid == 0) g_offs[NUM_NODES] = N_EDGES;
}

// ---- y0 = dis * w (fp16), coalesced; needs dis so runs after scan ----
__global__ void k_y0(const float4* __restrict__ w) {
    int i = blockIdx.x * blockDim.x + threadIdx.x;
    if (i < NUM_NODES * EMB_DIM / 4) {
        float4 v = w[i];
        float d = g_dis[i >> 4];          // 16 consecutive threads share node
        uint2 h;
        h.x = h2_to_u32(__floats2half2_rn(d * v.x, d * v.y));
        h.y = h2_to_u32(__floats2half2_rn(d * v.z, d * v.w));
        ((uint2*)g_y0)[i] = h;
    }
}

// ---- fill CSR: row index only; no norm, no random dis reads ----
__global__ void k_fill(const int* __restrict__ row, const int* __restrict__ col) {
    int e = blockIdx.x * blockDim.x + threadIdx.x;
    if (e >= N_EDGES) return;
    int c = col[e];
    int pos = g_offs[c] + atomicAdd(&g_cur[c], 1);
    g_csr[pos] = row[e];
}

// ---- add 8 fp16 values (one uint4) into 8 fp32 accumulators (no multiply) ----
__device__ __forceinline__ void sum8(float* a, uint4 hv) {
    float2 f0 = __half22float2(u32_to_h2(hv.x));
    float2 f1 = __half22float2(u32_to_h2(hv.y));
    float2 f2 = __half22float2(u32_to_h2(hv.z));
    float2 f3 = __half22float2(u32_to_h2(hv.w));
    a[0] += f0.x; a[1] += f0.y; a[2] += f1.x; a[3] += f1.y;
    a[4] += f2.x; a[5] += f2.y; a[6] += f3.x; a[7] += f3.y;
}

// ---- shared gather core: S[node chunk] = sum of y_src over incident edges ----
__device__ __forceinline__ void gather_core(const uint4* __restrict__ src,
                                            int s, int e, int lane, float* acc) {
    int j = s;
    for (; j + 8 <= e; j += 8) {
        int r0 = __ldg(&g_csr[j + 0]);
        int r1 = __ldg(&g_csr[j + 1]);
        int r2 = __ldg(&g_csr[j + 2]);
        int r3 = __ldg(&g_csr[j + 3]);
        int r4 = __ldg(&g_csr[j + 4]);
        int r5 = __ldg(&g_csr[j + 5]);
        int r6 = __ldg(&g_csr[j + 6]);
        int r7 = __ldg(&g_csr[j + 7]);
        uint4 v0 = __ldg(&src[r0 * 8 + lane]);
        uint4 v1 = __ldg(&src[r1 * 8 + lane]);
        uint4 v2 = __ldg(&src[r2 * 8 + lane]);
        uint4 v3 = __ldg(&src[r3 * 8 + lane]);
        uint4 v4 = __ldg(&src[r4 * 8 + lane]);
        uint4 v5 = __ldg(&src[r5 * 8 + lane]);
        uint4 v6 = __ldg(&src[r6 * 8 + lane]);
        uint4 v7 = __ldg(&src[r7 * 8 + lane]);
        sum8(acc, v0); sum8(acc, v1); sum8(acc, v2); sum8(acc, v3);
        sum8(acc, v4); sum8(acc, v5); sum8(acc, v6); sum8(acc, v7);
    }
    for (; j + 2 <= e; j += 2) {
        int ra = __ldg(&g_csr[j]);
        int rb = __ldg(&g_csr[j + 1]);
        uint4 va = __ldg(&src[ra * 8 + lane]);
        uint4 vb = __ldg(&src[rb * 8 + lane]);
        sum8(acc, va); sum8(acc, vb);
    }
    if (j < e) {
        int r = __ldg(&g_csr[j]);
        uint4 v = __ldg(&src[r * 8 + lane]);
        sum8(acc, v);
    }
}

// ---- layers 1 & 2: write ONLY the fp16 y for the next layer (no out traffic)
__global__ void k_gather12(int layer) {
    int t = blockIdx.x * blockDim.x + threadIdx.x;
    int node = t >> 3, lane = t & 7;
    if (node >= NUM_NODES) return;

    const uint4* src = (layer == 1) ? (const uint4*)g_y0 : (const uint4*)g_y1;
    float acc[8] = {0.f, 0.f, 0.f, 0.f, 0.f, 0.f, 0.f, 0.f};
    gather_core(src, g_offs[node], g_offs[node + 1], lane, acc);

    float d = g_dis[node];
    float d2 = d * d;                       // y_next = dis^2 * S
    uint4 h;
    h.x = h2_to_u32(__floats2half2_rn(d2 * acc[0], d2 * acc[1]));
    h.y = h2_to_u32(__floats2half2_rn(d2 * acc[2], d2 * acc[3]));
    h.z = h2_to_u32(__floats2half2_rn(d2 * acc[4], d2 * acc[5]));
    h.w = h2_to_u32(__floats2half2_rn(d2 * acc[6], d2 * acc[7]));
    int i16 = node * 8 + lane;
    if (layer == 1) ((uint4*)g_y1)[i16] = h;
    else            ((uint4*)g_y2)[i16] = h;
}

// ---- layer 3 + fused mean: out = 0.25*(w + dinv*y1 + dinv*y2 + dis*S3) ----
__global__ void k_gather_final(const float4* __restrict__ w,
                               float4* __restrict__ out) {
    int t = blockIdx.x * blockDim.x + threadIdx.x;
    int node = t >> 3, lane = t & 7;
    if (node >= NUM_NODES) return;

    float acc[8] = {0.f, 0.f, 0.f, 0.f, 0.f, 0.f, 0.f, 0.f};
    gather_core((const uint4*)g_y2, g_offs[node], g_offs[node + 1], lane, acc);

    float d  = g_dis[node];
    float di = g_dinv[node];
    int i16 = node * 8 + lane;
    uint4 h1 = ((const uint4*)g_y1)[i16];
    uint4 h2 = ((const uint4*)g_y2)[i16];
    float e1[8], e2[8];
    {
        float2 a = __half22float2(u32_to_h2(h1.x)), b = __half22float2(u32_to_h2(h1.y));
        float2 c = __half22float2(u32_to_h2(h1.z)), dq = __half22float2(u32_to_h2(h1.w));
        e1[0]=a.x; e1[1]=a.y; e1[2]=b.x; e1[3]=b.y; e1[4]=c.x; e1[5]=c.y; e1[6]=dq.x; e1[7]=dq.y;
    }
    {
        float2 a = __half22float2(u32_to_h2(h2.x)), b = __half22float2(u32_to_h2(h2.y));
        float2 c = __half22float2(u32_to_h2(h2.z)), dq = __half22float2(u32_to_h2(h2.w));
        e2[0]=a.x; e2[1]=a.y; e2[2]=b.x; e2[3]=b.y; e2[4]=c.x; e2[5]=c.y; e2[6]=dq.x; e2[7]=dq.y;
    }

    int i = node * 16 + lane * 2;
    float4 a0 = w[i], a1 = w[i + 1];
    const float q = 0.25f;
    out[i] = make_float4(
        q * (a0.x + di * (e1[0] + e2[0]) + d * acc[0]),
        q * (a0.y + di * (e1[1] + e2[1]) + d * acc[1]),
        q * (a0.z + di * (e1[2] + e2[2]) + d * acc[2]),
        q * (a0.w + di * (e1[3] + e2[3]) + d * acc[3]));
    out[i + 1] = make_float4(
        q * (a1.x + di * (e1[4] + e2[4]) + d * acc[4]),
        q * (a1.y + di * (e1[5] + e2[5]) + d * acc[5]),
        q * (a1.z + di * (e1[6] + e2[6]) + d * acc[6]),
        q * (a1.w + di * (e1[7] + e2[7]) + d * acc[7]));
}

extern "C" void kernel_launch(void* const* d_in, const int* in_sizes, int n_in,
                              void* d_out, int out_size) {
    const int*   edge = (const int*)d_in[0];     // [2, N_EDGES] int32
    const int*   row  = edge;
    const int*   col  = edge + N_EDGES;
    const float* w    = (const float*)d_in[1];   // [NUM_NODES, EMB_DIM] f32
    float*       out  = (float*)d_out;

    const int B = 256;
    const int nodes_blk = (NUM_NODES + B - 1) / B;
    const int edges_blk = (N_EDGES + B - 1) / B;
    const int vec_blk   = (NUM_NODES * EMB_DIM / 4 + B - 1) / B;
    const long long gth = (long long)NUM_NODES * 8;
    const int gather_blk = (int)((gth + B - 1) / B);

    // ---- build phase ----
    k_zero<<<nodes_blk, B>>>();
    k_count_deg<<<edges_blk, B>>>(col);
    k_scan_block<<<SCAN_GRID, SCAN_B>>>();
    k_scan_add<<<SCAN_GRID, SCAN_B>>>();
    k_y0<<<vec_blk, B>>>((const float4*)w);
    k_fill<<<edges_blk, B>>>(row, col);

    // ---- 3 propagation layers (natural node order: coalesced) ----
    k_gather12<<<gather_blk, B>>>(1);
    k_gather12<<<gather_blk, B>>>(2);
    k_gather_final<<<gather_blk, B>>>((const float4*)w, (float4*)out);
}